// round 14
// baseline (speedup 1.0000x reference)
#include <cuda_runtime.h>
#include <cuda_bf16.h>

#define kN 100000
#define kE 1600000
#define kG 256
#define kTiles 782          // ceil(kN/128)

// ---- scratch (static; no cudaMalloc). g_deg/g_gcnt/g_gacc zero at entry. ----
__device__ float4 g_agg[kN * 32];
__device__ float4 g_h1 [kN * 32];
__device__ int    g_deg[kN];
__device__ int    g_rowptr[kN + 1];
__device__ int    g_cursor[kN];
__device__ int    g_csr[kE];
__device__ int    g_gcnt[kG];
__device__ float  g_gacc[kG];

// ---- helpers ----------------------------------------------------------------
__device__ __forceinline__ unsigned bf2(float a, float b) {
    __nv_bfloat162 t = __floats2bfloat162_rn(a, b);
    return *(unsigned*)&t;
}
__device__ __forceinline__ float lo_of(float v) {
    return v - __bfloat162float(__float2bfloat16_rn(v));
}
// m16n8k16 row.col bf16 MMA, fp32 accum (baseline PTX, works on sm_100)
__device__ __forceinline__ void mma16816(float* d, const uint4& a,
                                         unsigned b0, unsigned b1) {
    asm volatile(
        "mma.sync.aligned.m16n8k16.row.col.f32.bf16.bf16.f32 "
        "{%0,%1,%2,%3}, {%4,%5,%6,%7}, {%8,%9}, {%0,%1,%2,%3};"
        : "+f"(d[0]), "+f"(d[1]), "+f"(d[2]), "+f"(d[3])
        : "r"(a.x), "r"(a.y), "r"(a.z), "r"(a.w), "r"(b0), "r"(b1));
}

// ---- CSR build (unchanged from 680us kernel) --------------------------------
__global__ void k_count(const int* __restrict__ ei, const int* __restrict__ batch) {
    int t = blockIdx.x * blockDim.x + threadIdx.x, st = gridDim.x * blockDim.x;
    const int* dstp = ei + kE;
    for (int e = t; e < kE; e += st) atomicAdd(&g_deg[dstp[e]], 1);
    for (int i = t; i < kN; i += st) atomicAdd(&g_gcnt[batch[i]], 1);
}
__global__ void k_scan() {
    __shared__ int wsums[32];
    __shared__ int sbase;
    int tid = threadIdx.x, lane = tid & 31, w = tid >> 5;
    if (tid == 0) sbase = 0;
    __syncthreads();
    for (int base = 0; base < kN; base += 1024) {
        int i = base + tid;
        int v = (i < kN) ? g_deg[i] : 0;
        int x = v;
#pragma unroll
        for (int off = 1; off < 32; off <<= 1) {
            int y = __shfl_up_sync(0xffffffffu, x, off);
            if (lane >= off) x += y;
        }
        if (lane == 31) wsums[w] = x;
        __syncthreads();
        if (w == 0) {
            int s = wsums[lane];
#pragma unroll
            for (int off = 1; off < 32; off <<= 1) {
                int y = __shfl_up_sync(0xffffffffu, s, off);
                if (lane >= off) s += y;
            }
            wsums[lane] = s;
        }
        __syncthreads();
        int incl = sbase + ((w > 0) ? wsums[w - 1] : 0) + x;
        if (i < kN) { g_rowptr[i + 1] = incl; g_cursor[i] = incl - v; }
        __syncthreads();
        if (tid == 1023) sbase = incl;
        __syncthreads();
    }
    if (tid == 0) g_rowptr[0] = 0;
}
__global__ void k_fill(const int* __restrict__ ei) {
    int t = blockIdx.x * blockDim.x + threadIdx.x, st = gridDim.x * blockDim.x;
    for (int e = t; e < kE; e += st) {
        int pos = atomicAdd(&g_cursor[ei[kE + e]], 1);
        g_csr[pos] = ei[e];
    }
}

// ---- gather (unchanged, MLP4) -----------------------------------------------
__global__ void k_gather(const float4* __restrict__ feat_ext, int use_h1) {
    const float4* feat = use_h1 ? (const float4*)g_h1 : feat_ext;
    int gw = (blockIdx.x * blockDim.x + threadIdx.x) >> 5;
    int lane = threadIdx.x & 31;
    int nw = (gridDim.x * blockDim.x) >> 5;
    for (int node = gw; node < kN; node += nw) {
        int beg = g_rowptr[node], end = g_rowptr[node + 1];
        float4 a0 = make_float4(0.f, 0.f, 0.f, 0.f), a1 = a0;
        for (int b = beg; b < end; b += 32) {
            int e = b + lane;
            int idx = (e < end) ? g_csr[e] : 0;
            int cnt = min(32, end - b), i = 0;
            for (; i + 4 <= cnt; i += 4) {
                int s0 = __shfl_sync(~0u, idx, i),     s1 = __shfl_sync(~0u, idx, i + 1);
                int s2 = __shfl_sync(~0u, idx, i + 2), s3 = __shfl_sync(~0u, idx, i + 3);
                float4 v0 = __ldg(&feat[s0 * 32 + lane]), v1 = __ldg(&feat[s1 * 32 + lane]);
                float4 v2 = __ldg(&feat[s2 * 32 + lane]), v3 = __ldg(&feat[s3 * 32 + lane]);
                a0.x += v0.x; a0.y += v0.y; a0.z += v0.z; a0.w += v0.w;
                a1.x += v1.x; a1.y += v1.y; a1.z += v1.z; a1.w += v1.w;
                a0.x += v2.x; a0.y += v2.y; a0.z += v2.z; a0.w += v2.w;
                a1.x += v3.x; a1.y += v3.y; a1.z += v3.z; a1.w += v3.w;
            }
            for (; i < cnt; i++) {
                int s0 = __shfl_sync(~0u, idx, i);
                float4 v0 = __ldg(&feat[s0 * 32 + lane]);
                a0.x += v0.x; a0.y += v0.y; a0.z += v0.z; a0.w += v0.w;
            }
        }
        float di = 1.0f / (float)max(end - beg, 1);
        a0.x = (a0.x + a1.x) * di; a0.y = (a0.y + a1.y) * di;
        a0.z = (a0.z + a1.z) * di; a0.w = (a0.w + a1.w) * di;
        g_agg[node * 32 + lane] = a0;
    }
}

// ---- HMMA SAGE layer --------------------------------------------------------
// Per 128-row tile: D = Ah@Wh + Ah@Wl + Al@Wh, A = [agg|x] (K=256), W = [Wl;Wr].
// All operands pre-packed in m16n8k16 FRAGMENT ORDER in smem:
//   Apack[(kt*8+mt)*32+lane] : uint4 = lane's 4 a-regs     (64 KB, repacked hi->lo)
//   Bpack[(kt*8+ntp)*32+lane]: uint4 = b-regs for nt=2*ntp, 2*ntp+1 (64 KB x2 splits)
// Warp = 4 m-tiles x 4 n-tiles (64 fp32 acc). Crossbar/tile ~4k cyc < HMMA ~6k.
#define OFF_BH 0
#define OFF_BL 65536
#define OFF_A  131072
#define SMEMSZ 196608
template <bool POOL>
__global__ void __launch_bounds__(256, 1)
k_mma_layer(const float4* __restrict__ xin_ext, int use_h1,
            const float* __restrict__ Wl, const float* __restrict__ bias,
            const float* __restrict__ Wr, const int* __restrict__ batch,
            const float* __restrict__ Wfc) {
    extern __shared__ unsigned char smem[];
    int tid = threadIdx.x, wid = tid >> 5, lane = tid & 31;
    int g = lane >> 2, tig = lane & 3;
    int mtg = wid >> 2, ntg = wid & 3;      // warp: m-tiles mtg*4.., n-tiles ntg*4..
    const float2* agg2 = (const float2*)g_agg;
    const float2* xin2 = use_h1 ? (const float2*)g_h1 : (const float2*)xin_ext;
    float2* h1f2 = (float2*)g_h1;

    // ---- pack B fragments (hi & lo splits), once per CTA --------------------
    uint4* Bh4 = (uint4*)(smem + OFF_BH);
    uint4* Bl4 = (uint4*)(smem + OFF_BL);
    for (int idx = tid; idx < 4096; idx += 256) {
        int l = idx & 31, ntp = (idx >> 5) & 7, kt = idx >> 8;
        int k0 = kt * 16 + (l & 3) * 2;
        uint4 hv, lv;
#pragma unroll
        for (int p = 0; p < 2; p++) {
            int n = (ntp * 2 + p) * 8 + (l >> 2);
            const float* w0 = (k0 < 128) ? (Wl + k0 * 128 + n) : (Wr + (k0 - 128) * 128 + n);
            float a = w0[0], b = w0[128], c = w0[8 * 128], d = w0[9 * 128];
            unsigned h0 = bf2(a, b), h1 = bf2(c, d);
            unsigned l0 = bf2(lo_of(a), lo_of(b)), l1 = bf2(lo_of(c), lo_of(d));
            if (p == 0) { hv.x = h0; hv.y = h1; lv.x = l0; lv.y = l1; }
            else        { hv.z = h0; hv.w = h1; lv.z = l0; lv.w = l1; }
        }
        Bh4[idx] = hv;
        Bl4[idx] = lv;
    }

    // per-lane column constants (cols c(ni) = (ntg*4+ni)*8 + tig*2, +1)
    float bs[4][2], wf[4][2];
#pragma unroll
    for (int ni = 0; ni < 4; ni++) {
        int c = (ntg * 4 + ni) * 8 + tig * 2;
        bs[ni][0] = bias[c]; bs[ni][1] = bias[c + 1];
        wf[ni][0] = POOL ? Wfc[c] : 0.f;
        wf[ni][1] = POOL ? Wfc[c + 1] : 0.f;
    }

    unsigned* Ap1 = (unsigned*)(smem + OFF_A);
    const uint4* Ap = (const uint4*)(smem + OFF_A);

    for (int tile = blockIdx.x; tile < kTiles; tile += gridDim.x) {
        int tb = tile << 7;
        __syncthreads();                    // protect Apack from previous tile
        // ---- pack A-hi fragments -------------------------------------------
        for (int idx = tid; idx < 16384; idx += 256) {
            int m = idx >> 7, t = idx & 127;      // t = k-pair index (k=2t,2t+1)
            int r = tb + m;
            float2 v = make_float2(0.f, 0.f);
            if (r < kN) v = (t < 64) ? agg2[r * 64 + t] : xin2[r * 64 + t - 64];
            int mt = m >> 4, mrow = m & 15;
            int kt = t >> 3, tp = t & 7;
            Ap1[((kt * 8 + mt) * 32 + (mrow & 7) * 4 + (tp & 3)) * 4
                + (tp >> 2) * 2 + (mrow >> 3)] = bf2(v.x, v.y);
        }
        __syncthreads();

        float d[4][4][4];
#pragma unroll
        for (int mi = 0; mi < 4; mi++)
#pragma unroll
            for (int ni = 0; ni < 4; ni++)
#pragma unroll
                for (int q = 0; q < 4; q++) d[mi][ni][q] = 0.f;

        // ---- passes 1+2: Ah@Bh + Ah@Bl -------------------------------------
        for (int kt = 0; kt < 16; kt++) {
            uint4 a[4], bh[2], bl[2];
#pragma unroll
            for (int mi = 0; mi < 4; mi++)
                a[mi] = Ap[(kt * 8 + mtg * 4 + mi) * 32 + lane];
#pragma unroll
            for (int p = 0; p < 2; p++) {
                bh[p] = Bh4[(kt * 8 + ntg * 2 + p) * 32 + lane];
                bl[p] = Bl4[(kt * 8 + ntg * 2 + p) * 32 + lane];
            }
#pragma unroll
            for (int mi = 0; mi < 4; mi++)
#pragma unroll
                for (int ni = 0; ni < 4; ni++) {
                    uint4 v = bh[ni >> 1];
                    mma16816(d[mi][ni], a[mi], (ni & 1) ? v.z : v.x,
                                               (ni & 1) ? v.w : v.y);
                }
#pragma unroll
            for (int mi = 0; mi < 4; mi++)
#pragma unroll
                for (int ni = 0; ni < 4; ni++) {
                    uint4 v = bl[ni >> 1];
                    mma16816(d[mi][ni], a[mi], (ni & 1) ? v.z : v.x,
                                               (ni & 1) ? v.w : v.y);
                }
        }
        __syncthreads();
        // ---- pack A-lo (overwrite) -----------------------------------------
        for (int idx = tid; idx < 16384; idx += 256) {
            int m = idx >> 7, t = idx & 127;
            int r = tb + m;
            float2 v = make_float2(0.f, 0.f);
            if (r < kN) v = (t < 64) ? agg2[r * 64 + t] : xin2[r * 64 + t - 64];
            int mt = m >> 4, mrow = m & 15;
            int kt = t >> 3, tp = t & 7;
            Ap1[((kt * 8 + mt) * 32 + (mrow & 7) * 4 + (tp & 3)) * 4
                + (tp >> 2) * 2 + (mrow >> 3)] = bf2(lo_of(v.x), lo_of(v.y));
        }
        __syncthreads();
        // ---- pass 3: Al@Bh --------------------------------------------------
        for (int kt = 0; kt < 16; kt++) {
            uint4 a[4], bh[2];
#pragma unroll
            for (int mi = 0; mi < 4; mi++)
                a[mi] = Ap[(kt * 8 + mtg * 4 + mi) * 32 + lane];
#pragma unroll
            for (int p = 0; p < 2; p++)
                bh[p] = Bh4[(kt * 8 + ntg * 2 + p) * 32 + lane];
#pragma unroll
            for (int mi = 0; mi < 4; mi++)
#pragma unroll
                for (int ni = 0; ni < 4; ni++) {
                    uint4 v = bh[ni >> 1];
                    mma16816(d[mi][ni], a[mi], (ni & 1) ? v.z : v.x,
                                               (ni & 1) ? v.w : v.y);
                }
        }

        // ---- epilogue -------------------------------------------------------
#pragma unroll
        for (int mi = 0; mi < 4; mi++) {
            int r0 = tb + (mtg * 4 + mi) * 16 + g;   // rows r0 and r0+8
            int r1 = r0 + 8;
            if (!POOL) {
#pragma unroll
                for (int ni = 0; ni < 4; ni++) {
                    int ch = ((ntg * 4 + ni) * 8 + tig * 2) >> 1;  // float2 col
                    float e00 = fmaxf(d[mi][ni][0] + bs[ni][0], 0.f);
                    float e01 = fmaxf(d[mi][ni][1] + bs[ni][1], 0.f);
                    float e10 = fmaxf(d[mi][ni][2] + bs[ni][0], 0.f);
                    float e11 = fmaxf(d[mi][ni][3] + bs[ni][1], 0.f);
                    if (r0 < kN) h1f2[r0 * 64 + ch] = make_float2(e00, e01);
                    if (r1 < kN) h1f2[r1 * 64 + ch] = make_float2(e10, e11);
                }
            } else {
                float s0 = 0.f, s1 = 0.f;
#pragma unroll
                for (int ni = 0; ni < 4; ni++) {
                    s0 += fmaxf(d[mi][ni][0] + bs[ni][0], 0.f) * wf[ni][0]
                        + fmaxf(d[mi][ni][1] + bs[ni][1], 0.f) * wf[ni][1];
                    s1 += fmaxf(d[mi][ni][2] + bs[ni][0], 0.f) * wf[ni][0]
                        + fmaxf(d[mi][ni][3] + bs[ni][1], 0.f) * wf[ni][1];
                }
                s0 += __shfl_xor_sync(~0u, s0, 1);
                s0 += __shfl_xor_sync(~0u, s0, 2);
                s1 += __shfl_xor_sync(~0u, s1, 1);
                s1 += __shfl_xor_sync(~0u, s1, 2);
                if (tig == 0) {
                    if (r0 < kN) atomicAdd(&g_gacc[batch[r0]], s0);
                    if (r1 < kN) atomicAdd(&g_gacc[batch[r1]], s1);
                }
            }
        }
    }
}

// ---- final readout + restore zero-invariant ---------------------------------
__global__ void k_final(const float* __restrict__ bfc, float* __restrict__ out) {
    int t = blockIdx.x * blockDim.x + threadIdx.x;
    if (blockIdx.x == 0 && threadIdx.x < kG) {
        int g = threadIdx.x;
        out[g] = g_gacc[g] / (float)max(g_gcnt[g], 1) + bfc[0];
        g_gacc[g] = 0.f;
        g_gcnt[g] = 0;
    }
    for (int i = t; i < kN; i += gridDim.x * blockDim.x) g_deg[i] = 0;
}

// ---- entry ------------------------------------------------------------------
extern "C" void kernel_launch(void* const* d_in, const int* in_sizes, int n_in,
                              void* d_out, int out_size) {
    const float4* x     = (const float4*)d_in[0];
    const int*    ei    = (const int*)d_in[1];    // int32 (JAX x64 disabled)
    const int*    batch = (const int*)d_in[2];
    const float*  W1l   = (const float*)d_in[3];
    const float*  b1    = (const float*)d_in[4];
    const float*  W1r   = (const float*)d_in[5];
    const float*  W2l   = (const float*)d_in[6];
    const float*  b2    = (const float*)d_in[7];
    const float*  W2r   = (const float*)d_in[8];
    const float*  Wfc   = (const float*)d_in[9];
    const float*  bfc   = (const float*)d_in[10];
    float*        out   = (float*)d_out;

    static int attr_done = 0;
    if (!attr_done) {
        cudaFuncSetAttribute(k_mma_layer<false>,
                             cudaFuncAttributeMaxDynamicSharedMemorySize, SMEMSZ);
        cudaFuncSetAttribute(k_mma_layer<true>,
                             cudaFuncAttributeMaxDynamicSharedMemorySize, SMEMSZ);
        attr_done = 1;
    }

    k_count<<<512, 256>>>(ei, batch);
    k_scan<<<1, 1024>>>();
    k_fill<<<512, 256>>>(ei);

    k_gather<<<1024, 256>>>(x, 0);
    k_mma_layer<false><<<148, 256, SMEMSZ>>>(x, 0, W1l, b1, W1r, batch, Wfc);

    k_gather<<<1024, 256>>>(x, 1);
    k_mma_layer<true><<<148, 256, SMEMSZ>>>(x, 1, W2l, b2, W2r, batch, Wfc);

    k_final<<<512, 256>>>(bfc, out);
}

// round 15
// speedup vs baseline: 1.2249x; 1.2249x over previous
#include <cuda_runtime.h>
#include <cuda_bf16.h>

#define kN 100000
#define kE 1600000
#define kG 256
#define kTiles 782          // ceil(kN/128)

// ---- scratch (static; no cudaMalloc). g_deg/g_gcnt/g_gacc zero at entry. ----
__device__ float4 g_agg[kN * 32];
__device__ float4 g_h1 [kN * 32];
__device__ int    g_deg[kN];
__device__ int    g_rowptr[kN + 1];
__device__ int    g_cursor[kN];
__device__ int    g_csr[kE];
__device__ int    g_gcnt[kG];
__device__ float  g_gacc[kG];

// ---- helpers ----------------------------------------------------------------
__device__ __forceinline__ unsigned bf2(float a, float b) {
    __nv_bfloat162 t = __floats2bfloat162_rn(a, b);
    return *(unsigned*)&t;
}
__device__ __forceinline__ float lo_of(float v) {
    return v - __bfloat162float(__float2bfloat16_rn(v));
}
// m16n8k16 row.col bf16 MMA, fp32 accum. float4& keeps accumulators in regs.
__device__ __forceinline__ void mma16816(float4& d, const uint4& a,
                                         unsigned b0, unsigned b1) {
    asm volatile(
        "mma.sync.aligned.m16n8k16.row.col.f32.bf16.bf16.f32 "
        "{%0,%1,%2,%3}, {%4,%5,%6,%7}, {%8,%9}, {%0,%1,%2,%3};"
        : "+f"(d.x), "+f"(d.y), "+f"(d.z), "+f"(d.w)
        : "r"(a.x), "r"(a.y), "r"(a.z), "r"(a.w), "r"(b0), "r"(b1));
}

// ---- CSR build --------------------------------------------------------------
__global__ void k_count(const int* __restrict__ ei, const int* __restrict__ batch) {
    int t = blockIdx.x * blockDim.x + threadIdx.x, st = gridDim.x * blockDim.x;
    const int* dstp = ei + kE;
    for (int e = t; e < kE; e += st) atomicAdd(&g_deg[dstp[e]], 1);
    for (int i = t; i < kN; i += st) atomicAdd(&g_gcnt[batch[i]], 1);
}
__global__ void k_scan() {
    __shared__ int wsums[32];
    __shared__ int sbase;
    int tid = threadIdx.x, lane = tid & 31, w = tid >> 5;
    if (tid == 0) sbase = 0;
    __syncthreads();
    for (int base = 0; base < kN; base += 1024) {
        int i = base + tid;
        int v = (i < kN) ? g_deg[i] : 0;
        int x = v;
#pragma unroll
        for (int off = 1; off < 32; off <<= 1) {
            int y = __shfl_up_sync(0xffffffffu, x, off);
            if (lane >= off) x += y;
        }
        if (lane == 31) wsums[w] = x;
        __syncthreads();
        if (w == 0) {
            int s = wsums[lane];
#pragma unroll
            for (int off = 1; off < 32; off <<= 1) {
                int y = __shfl_up_sync(0xffffffffu, s, off);
                if (lane >= off) s += y;
            }
            wsums[lane] = s;
        }
        __syncthreads();
        int incl = sbase + ((w > 0) ? wsums[w - 1] : 0) + x;
        if (i < kN) { g_rowptr[i + 1] = incl; g_cursor[i] = incl - v; }
        __syncthreads();
        if (tid == 1023) sbase = incl;
        __syncthreads();
    }
    if (tid == 0) g_rowptr[0] = 0;
}
__global__ void k_fill(const int* __restrict__ ei) {
    int t = blockIdx.x * blockDim.x + threadIdx.x, st = gridDim.x * blockDim.x;
    for (int e = t; e < kE; e += st) {
        int pos = atomicAdd(&g_cursor[ei[kE + e]], 1);
        g_csr[pos] = ei[e];
    }
}

// ---- gather (MLP4) ----------------------------------------------------------
__global__ void k_gather(const float4* __restrict__ feat_ext, int use_h1) {
    const float4* feat = use_h1 ? (const float4*)g_h1 : feat_ext;
    int gw = (blockIdx.x * blockDim.x + threadIdx.x) >> 5;
    int lane = threadIdx.x & 31;
    int nw = (gridDim.x * blockDim.x) >> 5;
    for (int node = gw; node < kN; node += nw) {
        int beg = g_rowptr[node], end = g_rowptr[node + 1];
        float4 a0 = make_float4(0.f, 0.f, 0.f, 0.f), a1 = a0;
        for (int b = beg; b < end; b += 32) {
            int e = b + lane;
            int idx = (e < end) ? g_csr[e] : 0;
            int cnt = min(32, end - b), i = 0;
            for (; i + 4 <= cnt; i += 4) {
                int s0 = __shfl_sync(~0u, idx, i),     s1 = __shfl_sync(~0u, idx, i + 1);
                int s2 = __shfl_sync(~0u, idx, i + 2), s3 = __shfl_sync(~0u, idx, i + 3);
                float4 v0 = __ldg(&feat[s0 * 32 + lane]), v1 = __ldg(&feat[s1 * 32 + lane]);
                float4 v2 = __ldg(&feat[s2 * 32 + lane]), v3 = __ldg(&feat[s3 * 32 + lane]);
                a0.x += v0.x; a0.y += v0.y; a0.z += v0.z; a0.w += v0.w;
                a1.x += v1.x; a1.y += v1.y; a1.z += v1.z; a1.w += v1.w;
                a0.x += v2.x; a0.y += v2.y; a0.z += v2.z; a0.w += v2.w;
                a1.x += v3.x; a1.y += v3.y; a1.z += v3.z; a1.w += v3.w;
            }
            for (; i < cnt; i++) {
                int s0 = __shfl_sync(~0u, idx, i);
                float4 v0 = __ldg(&feat[s0 * 32 + lane]);
                a0.x += v0.x; a0.y += v0.y; a0.z += v0.z; a0.w += v0.w;
            }
        }
        float di = 1.0f / (float)max(end - beg, 1);
        a0.x = (a0.x + a1.x) * di; a0.y = (a0.y + a1.y) * di;
        a0.z = (a0.z + a1.z) * di; a0.w = (a0.w + a1.w) * di;
        g_agg[node * 32 + lane] = a0;
    }
}

// ---- HMMA SAGE layer --------------------------------------------------------
// Per 128-row tile: D = Ah@Wh + Ah@Wl + Al@Wh, A = [agg|x] (K=256), W = [Wl;Wr].
// Fragment-packed smem (layout identical to the verified R14 kernel):
//   Apack[(kt*8+mt)*32+lane]: uint4 = {v(r0,t0), v(r1,t0), v(r0,t1), v(r1,t1)}
//     with r0 = mt*16 + (lane>>2), r1 = r0+8, t0 = kt*8 + (lane&3), t1 = t0+4
//   Bpack[(kt*8+ntp)*32+lane]: uint4 = b-frags for nt = 2ntp, 2ntp+1
// Pack: warp w packs m-tile w (per-thread: 4 guarded LDG.64 + 1 STS.128).
// Warp = 4 m-tiles x 4 n-tiles, accumulators float4 acc[4][4] (register-resident).
#define OFF_BH 0
#define OFF_BL 65536
#define OFF_A  131072
#define SMEMSZ 196608
template <bool POOL>
__global__ void __launch_bounds__(256, 1)
k_mma_layer(const float4* __restrict__ xin_ext, int use_h1,
            const float* __restrict__ Wl, const float* __restrict__ bias,
            const float* __restrict__ Wr, const int* __restrict__ batch,
            const float* __restrict__ Wfc) {
    extern __shared__ unsigned char smem[];
    int tid = threadIdx.x, wid = tid >> 5, lane = tid & 31;
    int g = lane >> 2, tig = lane & 3;
    int mtg = wid >> 2, ntg = wid & 3;
    const float2* agg2 = (const float2*)g_agg;
    const float2* xin2 = use_h1 ? (const float2*)g_h1 : (const float2*)xin_ext;
    float2* h1f2 = (float2*)g_h1;

    // ---- pack B fragments (hi & lo splits), once per CTA --------------------
    uint4* Bh4 = (uint4*)(smem + OFF_BH);
    uint4* Bl4 = (uint4*)(smem + OFF_BL);
    for (int idx = tid; idx < 4096; idx += 256) {
        int l = idx & 31, ntp = (idx >> 5) & 7, kt = idx >> 8;
        int k0 = kt * 16 + (l & 3) * 2;
        uint4 hv, lv;
#pragma unroll
        for (int p = 0; p < 2; p++) {
            int n = (ntp * 2 + p) * 8 + (l >> 2);
            const float* w0 = (k0 < 128) ? (Wl + k0 * 128 + n) : (Wr + (k0 - 128) * 128 + n);
            float a = w0[0], b = w0[128], c = w0[8 * 128], d = w0[9 * 128];
            unsigned h0 = bf2(a, b), h1 = bf2(c, d);
            unsigned l0 = bf2(lo_of(a), lo_of(b)), l1 = bf2(lo_of(c), lo_of(d));
            if (p == 0) { hv.x = h0; hv.y = h1; lv.x = l0; lv.y = l1; }
            else        { hv.z = h0; hv.w = h1; lv.z = l0; lv.w = l1; }
        }
        Bh4[idx] = hv;
        Bl4[idx] = lv;
    }

    // per-lane column constants (cols c(ni) = (ntg*4+ni)*8 + tig*2, +1)
    float bs[4][2], wf[4][2];
#pragma unroll
    for (int ni = 0; ni < 4; ni++) {
        int c = (ntg * 4 + ni) * 8 + tig * 2;
        bs[ni][0] = bias[c]; bs[ni][1] = bias[c + 1];
        wf[ni][0] = POOL ? Wfc[c] : 0.f;
        wf[ni][1] = POOL ? Wfc[c + 1] : 0.f;
    }

    uint4* Ap = (uint4*)(smem + OFF_A);

    for (int tile = blockIdx.x; tile < kTiles; tile += gridDim.x) {
        int tb = tile << 7;
        // per-thread pack coordinates: warp wid owns m-tile wid
        int r0 = tb + wid * 16 + g, r1 = r0 + 8;
        bool ok0 = r0 < kN, ok1 = r1 < kN;
        const float2* pa0 = agg2 + (size_t)r0 * 64;
        const float2* pa1 = agg2 + (size_t)r1 * 64;
        const float2* px0 = xin2 + (size_t)r0 * 64;
        const float2* px1 = xin2 + (size_t)r1 * 64;
        uint4* dst = Ap + wid * 32 + lane;
        const float2 z2 = make_float2(0.f, 0.f);

        __syncthreads();                    // protect Apack from previous tile
        // ---- pack A-hi ------------------------------------------------------
#pragma unroll
        for (int kt = 0; kt < 16; kt++) {
            const float2* s0 = (kt < 8) ? pa0 : px0;
            const float2* s1 = (kt < 8) ? pa1 : px1;
            int t0 = (kt & 7) * 8 + tig;
            float2 v00 = ok0 ? __ldg(&s0[t0])     : z2;
            float2 v01 = ok0 ? __ldg(&s0[t0 + 4]) : z2;
            float2 v10 = ok1 ? __ldg(&s1[t0])     : z2;
            float2 v11 = ok1 ? __ldg(&s1[t0 + 4]) : z2;
            dst[kt * 256] = make_uint4(bf2(v00.x, v00.y), bf2(v10.x, v10.y),
                                       bf2(v01.x, v01.y), bf2(v11.x, v11.y));
        }
        __syncthreads();

        float4 acc[4][4];
#pragma unroll
        for (int mi = 0; mi < 4; mi++)
#pragma unroll
            for (int ni = 0; ni < 4; ni++)
                acc[mi][ni] = make_float4(0.f, 0.f, 0.f, 0.f);

        // ---- passes 1+2: Ah@Bh + Ah@Bl -------------------------------------
        for (int kt = 0; kt < 16; kt++) {
            uint4 a[4], bh[2], bl[2];
#pragma unroll
            for (int mi = 0; mi < 4; mi++)
                a[mi] = Ap[(kt * 8 + mtg * 4 + mi) * 32 + lane];
#pragma unroll
            for (int p = 0; p < 2; p++) {
                bh[p] = Bh4[(kt * 8 + ntg * 2 + p) * 32 + lane];
                bl[p] = Bl4[(kt * 8 + ntg * 2 + p) * 32 + lane];
            }
#pragma unroll
            for (int mi = 0; mi < 4; mi++)
#pragma unroll
                for (int ni = 0; ni < 4; ni++) {
                    uint4 v = bh[ni >> 1];
                    mma16816(acc[mi][ni], a[mi], (ni & 1) ? v.z : v.x,
                                                 (ni & 1) ? v.w : v.y);
                }
#pragma unroll
            for (int mi = 0; mi < 4; mi++)
#pragma unroll
                for (int ni = 0; ni < 4; ni++) {
                    uint4 v = bl[ni >> 1];
                    mma16816(acc[mi][ni], a[mi], (ni & 1) ? v.z : v.x,
                                                 (ni & 1) ? v.w : v.y);
                }
        }
        __syncthreads();
        // ---- pack A-lo (overwrite) -----------------------------------------
#pragma unroll
        for (int kt = 0; kt < 16; kt++) {
            const float2* s0 = (kt < 8) ? pa0 : px0;
            const float2* s1 = (kt < 8) ? pa1 : px1;
            int t0 = (kt & 7) * 8 + tig;
            float2 v00 = ok0 ? __ldg(&s0[t0])     : z2;
            float2 v01 = ok0 ? __ldg(&s0[t0 + 4]) : z2;
            float2 v10 = ok1 ? __ldg(&s1[t0])     : z2;
            float2 v11 = ok1 ? __ldg(&s1[t0 + 4]) : z2;
            dst[kt * 256] = make_uint4(
                bf2(lo_of(v00.x), lo_of(v00.y)), bf2(lo_of(v10.x), lo_of(v10.y)),
                bf2(lo_of(v01.x), lo_of(v01.y)), bf2(lo_of(v11.x), lo_of(v11.y)));
        }
        __syncthreads();
        // ---- pass 3: Al@Bh --------------------------------------------------
        for (int kt = 0; kt < 16; kt++) {
            uint4 a[4], bh[2];
#pragma unroll
            for (int mi = 0; mi < 4; mi++)
                a[mi] = Ap[(kt * 8 + mtg * 4 + mi) * 32 + lane];
#pragma unroll
            for (int p = 0; p < 2; p++)
                bh[p] = Bh4[(kt * 8 + ntg * 2 + p) * 32 + lane];
#pragma unroll
            for (int mi = 0; mi < 4; mi++)
#pragma unroll
                for (int ni = 0; ni < 4; ni++) {
                    uint4 v = bh[ni >> 1];
                    mma16816(acc[mi][ni], a[mi], (ni & 1) ? v.z : v.x,
                                                 (ni & 1) ? v.w : v.y);
                }
        }

        // ---- epilogue -------------------------------------------------------
#pragma unroll
        for (int mi = 0; mi < 4; mi++) {
            int er0 = tb + (mtg * 4 + mi) * 16 + g;   // rows er0 and er0+8
            int er1 = er0 + 8;
            if (!POOL) {
#pragma unroll
                for (int ni = 0; ni < 4; ni++) {
                    int ch = ((ntg * 4 + ni) * 8 + tig * 2) >> 1;  // float2 col
                    float e00 = fmaxf(acc[mi][ni].x + bs[ni][0], 0.f);
                    float e01 = fmaxf(acc[mi][ni].y + bs[ni][1], 0.f);
                    float e10 = fmaxf(acc[mi][ni].z + bs[ni][0], 0.f);
                    float e11 = fmaxf(acc[mi][ni].w + bs[ni][1], 0.f);
                    if (er0 < kN) h1f2[er0 * 64 + ch] = make_float2(e00, e01);
                    if (er1 < kN) h1f2[er1 * 64 + ch] = make_float2(e10, e11);
                }
            } else {
                float s0 = 0.f, s1 = 0.f;
#pragma unroll
                for (int ni = 0; ni < 4; ni++) {
                    s0 += fmaxf(acc[mi][ni].x + bs[ni][0], 0.f) * wf[ni][0]
                        + fmaxf(acc[mi][ni].y + bs[ni][1], 0.f) * wf[ni][1];
                    s1 += fmaxf(acc[mi][ni].z + bs[ni][0], 0.f) * wf[ni][0]
                        + fmaxf(acc[mi][ni].w + bs[ni][1], 0.f) * wf[ni][1];
                }
                s0 += __shfl_xor_sync(~0u, s0, 1);
                s0 += __shfl_xor_sync(~0u, s0, 2);
                s1 += __shfl_xor_sync(~0u, s1, 1);
                s1 += __shfl_xor_sync(~0u, s1, 2);
                if (tig == 0) {
                    if (er0 < kN) atomicAdd(&g_gacc[batch[er0]], s0);
                    if (er1 < kN) atomicAdd(&g_gacc[batch[er1]], s1);
                }
            }
        }
    }
}

// ---- final readout + restore zero-invariant ---------------------------------
__global__ void k_final(const float* __restrict__ bfc, float* __restrict__ out) {
    int t = blockIdx.x * blockDim.x + threadIdx.x;
    if (blockIdx.x == 0 && threadIdx.x < kG) {
        int g = threadIdx.x;
        out[g] = g_gacc[g] / (float)max(g_gcnt[g], 1) + bfc[0];
        g_gacc[g] = 0.f;
        g_gcnt[g] = 0;
    }
    for (int i = t; i < kN; i += gridDim.x * blockDim.x) g_deg[i] = 0;
}

// ---- entry ------------------------------------------------------------------
extern "C" void kernel_launch(void* const* d_in, const int* in_sizes, int n_in,
                              void* d_out, int out_size) {
    const float4* x     = (const float4*)d_in[0];
    const int*    ei    = (const int*)d_in[1];    // int32 (JAX x64 disabled)
    const int*    batch = (const int*)d_in[2];
    const float*  W1l   = (const float*)d_in[3];
    const float*  b1    = (const float*)d_in[4];
    const float*  W1r   = (const float*)d_in[5];
    const float*  W2l   = (const float*)d_in[6];
    const float*  b2    = (const float*)d_in[7];
    const float*  W2r   = (const float*)d_in[8];
    const float*  Wfc   = (const float*)d_in[9];
    const float*  bfc   = (const float*)d_in[10];
    float*        out   = (float*)d_out;

    static int attr_done = 0;
    if (!attr_done) {
        cudaFuncSetAttribute(k_mma_layer<false>,
                             cudaFuncAttributeMaxDynamicSharedMemorySize, SMEMSZ);
        cudaFuncSetAttribute(k_mma_layer<true>,
                             cudaFuncAttributeMaxDynamicSharedMemorySize, SMEMSZ);
        attr_done = 1;
    }

    k_count<<<512, 256>>>(ei, batch);
    k_scan<<<1, 1024>>>();
    k_fill<<<512, 256>>>(ei);

    // DIAGNOSTIC dummy (our 4th launch -> the one ncu captures). Reads stale
    // g_agg (deterministic: previous call's gather output; zeros on call 1) and
    // writes g_h1, which the real layer-1 pass below fully overwrites.
    k_mma_layer<false><<<148, 256, SMEMSZ>>>(x, 0, W1l, b1, W1r, batch, Wfc);

    // Layer 1
    k_gather<<<1024, 256>>>(x, 0);
    k_mma_layer<false><<<148, 256, SMEMSZ>>>(x, 0, W1l, b1, W1r, batch, Wfc);

    // Layer 2 (+ fused pooled readout)
    k_gather<<<1024, 256>>>(x, 1);
    k_mma_layer<true><<<148, 256, SMEMSZ>>>(x, 1, W2l, b2, W2r, batch, Wfc);

    k_final<<<512, 256>>>(bfc, out);
}

// round 16
// speedup vs baseline: 1.7091x; 1.3952x over previous
#include <cuda_runtime.h>
#include <cuda_bf16.h>

#define kN 100000
#define kE 1600000
#define kG 256
#define kT64 1563           // ceil(kN/64)
#define SCANB 98            // ceil(kN/1024)

// ---- scratch (static; no cudaMalloc). g_deg/g_gcnt/g_gacc zero at entry. ----
__device__ float4 g_agg[kN * 32];
__device__ float4 g_h1 [kN * 32];
__device__ int    g_deg[kN];
__device__ int    g_rowptr[kN + 1];
__device__ int    g_cursor[kN];
__device__ int    g_csr[kE];
__device__ int    g_bsum[SCANB];
__device__ int    g_gcnt[kG];
__device__ float  g_gacc[kG];

// ---- helpers ----------------------------------------------------------------
__device__ __forceinline__ unsigned bf2(float a, float b) {
    __nv_bfloat162 t = __floats2bfloat162_rn(a, b);
    return *(unsigned*)&t;
}
__device__ __forceinline__ float lo_of(float v) {
    return v - __bfloat162float(__float2bfloat16_rn(v));
}
// m16n8k16 row.col bf16 MMA, fp32 accum. float4& keeps accumulators in regs.
__device__ __forceinline__ void mma16816(float4& d, const uint4& a,
                                         unsigned b0, unsigned b1) {
    asm volatile(
        "mma.sync.aligned.m16n8k16.row.col.f32.bf16.bf16.f32 "
        "{%0,%1,%2,%3}, {%4,%5,%6,%7}, {%8,%9}, {%0,%1,%2,%3};"
        : "+f"(d.x), "+f"(d.y), "+f"(d.z), "+f"(d.w)
        : "r"(a.x), "r"(a.y), "r"(a.z), "r"(a.w), "r"(b0), "r"(b1));
}

// ---- CSR build --------------------------------------------------------------
__global__ void k_count(const int* __restrict__ ei, const int* __restrict__ batch) {
    int t = blockIdx.x * blockDim.x + threadIdx.x, st = gridDim.x * blockDim.x;
    const int* dstp = ei + kE;
    for (int e = t; e < kE; e += st) atomicAdd(&g_deg[dstp[e]], 1);
    for (int i = t; i < kN; i += st) atomicAdd(&g_gcnt[batch[i]], 1);
}
// per-block inclusive scan of g_deg -> partial rowptr/cursor + block sums
__global__ void k_scanA() {
    __shared__ int wsums[32];
    int tid = threadIdx.x, lane = tid & 31, w = tid >> 5;
    int i = blockIdx.x * 1024 + tid;
    int v = (i < kN) ? g_deg[i] : 0;
    int x = v;
#pragma unroll
    for (int off = 1; off < 32; off <<= 1) {
        int y = __shfl_up_sync(0xffffffffu, x, off);
        if (lane >= off) x += y;
    }
    if (lane == 31) wsums[w] = x;
    __syncthreads();
    if (w == 0) {
        int s = wsums[lane];
#pragma unroll
        for (int off = 1; off < 32; off <<= 1) {
            int y = __shfl_up_sync(0xffffffffu, s, off);
            if (lane >= off) s += y;
        }
        wsums[lane] = s;
    }
    __syncthreads();
    int incl = ((w > 0) ? wsums[w - 1] : 0) + x;
    if (i < kN) { g_rowptr[i + 1] = incl; g_cursor[i] = incl - v; }
    if (tid == 1023) g_bsum[blockIdx.x] = incl;   // block total
}
// exclusive scan of the SCANB block sums (single small block)
__global__ void k_scanB() {
    __shared__ int s[128];
    int t = threadIdx.x;
    int v = (t < SCANB) ? g_bsum[t] : 0;
    s[t] = v;
    __syncthreads();
#pragma unroll
    for (int off = 1; off < 128; off <<= 1) {
        int y = (t >= off) ? s[t - off] : 0;
        __syncthreads();
        s[t] += y;
        __syncthreads();
    }
    if (t < SCANB) g_bsum[t] = s[t] - v;          // exclusive prefix
}
__global__ void k_scanC() {
    int i = blockIdx.x * 1024 + threadIdx.x;
    if (i < kN) {
        int base = g_bsum[blockIdx.x];
        g_rowptr[i + 1] += base;
        g_cursor[i]     += base;
    }
    if (i == 0) g_rowptr[0] = 0;
}
__global__ void k_fill(const int* __restrict__ ei) {
    int t = blockIdx.x * blockDim.x + threadIdx.x, st = gridDim.x * blockDim.x;
    for (int e = t; e < kE; e += st) {
        int pos = atomicAdd(&g_cursor[ei[kE + e]], 1);
        g_csr[pos] = ei[e];
    }
}

// ---- gather (MLP4) ----------------------------------------------------------
__global__ void k_gather(const float4* __restrict__ feat_ext, int use_h1) {
    const float4* feat = use_h1 ? (const float4*)g_h1 : feat_ext;
    int gw = (blockIdx.x * blockDim.x + threadIdx.x) >> 5;
    int lane = threadIdx.x & 31;
    int nw = (gridDim.x * blockDim.x) >> 5;
    for (int node = gw; node < kN; node += nw) {
        int beg = g_rowptr[node], end = g_rowptr[node + 1];
        float4 a0 = make_float4(0.f, 0.f, 0.f, 0.f), a1 = a0;
        for (int b = beg; b < end; b += 32) {
            int e = b + lane;
            int idx = (e < end) ? g_csr[e] : 0;
            int cnt = min(32, end - b), i = 0;
            for (; i + 4 <= cnt; i += 4) {
                int s0 = __shfl_sync(~0u, idx, i),     s1 = __shfl_sync(~0u, idx, i + 1);
                int s2 = __shfl_sync(~0u, idx, i + 2), s3 = __shfl_sync(~0u, idx, i + 3);
                float4 v0 = __ldg(&feat[s0 * 32 + lane]), v1 = __ldg(&feat[s1 * 32 + lane]);
                float4 v2 = __ldg(&feat[s2 * 32 + lane]), v3 = __ldg(&feat[s3 * 32 + lane]);
                a0.x += v0.x; a0.y += v0.y; a0.z += v0.z; a0.w += v0.w;
                a1.x += v1.x; a1.y += v1.y; a1.z += v1.z; a1.w += v1.w;
                a0.x += v2.x; a0.y += v2.y; a0.z += v2.z; a0.w += v2.w;
                a1.x += v3.x; a1.y += v3.y; a1.z += v3.z; a1.w += v3.w;
            }
            for (; i < cnt; i++) {
                int s0 = __shfl_sync(~0u, idx, i);
                float4 v0 = __ldg(&feat[s0 * 32 + lane]);
                a0.x += v0.x; a0.y += v0.y; a0.z += v0.z; a0.w += v0.w;
            }
        }
        float di = 1.0f / (float)max(end - beg, 1);
        a0.x = (a0.x + a1.x) * di; a0.y = (a0.y + a1.y) * di;
        a0.z = (a0.z + a1.z) * di; a0.w = (a0.w + a1.w) * di;
        g_agg[node * 32 + lane] = a0;
    }
}

// ---- HMMA SAGE layer (M=64 tiles, both A splits resident, fused passes) -----
// Per 64-row tile: D = Ah@Bh + Ah@Bl + Al@Bh fused in ONE kt loop (24 MMA/kt).
// Fragment layouts identical to the numerically-verified R14/R15 kernel:
//   Apack[(kt*4+mt)*32+lane]: uint4 = {v(r0,t0), v(r1,t0), v(r0,t1), v(r1,t1)}
//     r0 = mt*16+(lane>>2), r1 = r0+8, t0 = kt*8+(lane&3), t1 = t0+4
//   Bpack[(kt*8+ntp)*32+lane]: uint4 = b-frags for n-tiles 2ntp, 2ntp+1
// One pack phase per tile (reads agg/x once, emits hi AND lo). 2 syncs/tile.
// Warp = 2 m-tiles x 4 n-tiles (acc float4[2][4], register-resident).
#define OFF_BH 0
#define OFF_BL 65536
#define OFF_AH 131072
#define OFF_AL 163840
#define SMEMSZ 196608
template <bool POOL>
__global__ void __launch_bounds__(256, 1)
k_mma_layer(const float4* __restrict__ xin_ext, int use_h1,
            const float* __restrict__ Wl, const float* __restrict__ bias,
            const float* __restrict__ Wr, const int* __restrict__ batch,
            const float* __restrict__ Wfc) {
    extern __shared__ unsigned char smem[];
    int tid = threadIdx.x, wid = tid >> 5, lane = tid & 31;
    int g = lane >> 2, tig = lane & 3;
    int mtg = wid >> 2, ntg = wid & 3;      // MMA: 2 mtg x 4 ntg
    const float2* agg2 = (const float2*)g_agg;
    const float2* xin2 = use_h1 ? (const float2*)g_h1 : (const float2*)xin_ext;
    float2* h1f2 = (float2*)g_h1;

    // ---- pack B fragments (hi & lo splits), once per CTA --------------------
    uint4* Bh4 = (uint4*)(smem + OFF_BH);
    uint4* Bl4 = (uint4*)(smem + OFF_BL);
    for (int idx = tid; idx < 4096; idx += 256) {
        int l = idx & 31, ntp = (idx >> 5) & 7, kt = idx >> 8;
        int k0 = kt * 16 + (l & 3) * 2;
        uint4 hv, lv;
#pragma unroll
        for (int p = 0; p < 2; p++) {
            int n = (ntp * 2 + p) * 8 + (l >> 2);
            const float* w0 = (k0 < 128) ? (Wl + k0 * 128 + n) : (Wr + (k0 - 128) * 128 + n);
            float a = w0[0], b = w0[128], c = w0[8 * 128], d = w0[9 * 128];
            unsigned h0 = bf2(a, b), h1 = bf2(c, d);
            unsigned l0 = bf2(lo_of(a), lo_of(b)), l1 = bf2(lo_of(c), lo_of(d));
            if (p == 0) { hv.x = h0; hv.y = h1; lv.x = l0; lv.y = l1; }
            else        { hv.z = h0; hv.w = h1; lv.z = l0; lv.w = l1; }
        }
        Bh4[idx] = hv;
        Bl4[idx] = lv;
    }

    // per-lane column constants (cols c(ni) = (ntg*4+ni)*8 + tig*2, +1)
    float bs[4][2], wf[4][2];
#pragma unroll
    for (int ni = 0; ni < 4; ni++) {
        int c = (ntg * 4 + ni) * 8 + tig * 2;
        bs[ni][0] = bias[c]; bs[ni][1] = bias[c + 1];
        wf[ni][0] = POOL ? Wfc[c] : 0.f;
        wf[ni][1] = POOL ? Wfc[c + 1] : 0.f;
    }

    uint4* Ah4 = (uint4*)(smem + OFF_AH);
    uint4* Al4 = (uint4*)(smem + OFF_AL);
    int pmt = wid & 3, pkh = wid >> 2;      // pack: warp -> m-tile pmt, kt-half pkh

    for (int tile = blockIdx.x; tile < kT64; tile += gridDim.x) {
        int tb = tile << 6;
        // pack coordinates
        int r0 = tb + pmt * 16 + g, r1 = r0 + 8;
        bool ok0 = r0 < kN, ok1 = r1 < kN;
        const float2* pa0 = agg2 + (size_t)r0 * 64;
        const float2* pa1 = agg2 + (size_t)r1 * 64;
        const float2* px0 = xin2 + (size_t)r0 * 64;
        const float2* px1 = xin2 + (size_t)r1 * 64;
        const float2 z2 = make_float2(0.f, 0.f);

        __syncthreads();                    // protect A buffers from prev tile
        // ---- single pack phase: hi AND lo from one read ---------------------
#pragma unroll
        for (int ki = 0; ki < 8; ki++) {
            int kt = pkh * 8 + ki;
            const float2* s0 = (kt < 8) ? pa0 : px0;
            const float2* s1 = (kt < 8) ? pa1 : px1;
            int t0 = (kt & 7) * 8 + tig;
            float2 v00 = ok0 ? __ldg(&s0[t0])     : z2;
            float2 v01 = ok0 ? __ldg(&s0[t0 + 4]) : z2;
            float2 v10 = ok1 ? __ldg(&s1[t0])     : z2;
            float2 v11 = ok1 ? __ldg(&s1[t0 + 4]) : z2;
            int fi = (kt * 4 + pmt) * 32 + lane;
            Ah4[fi] = make_uint4(bf2(v00.x, v00.y), bf2(v10.x, v10.y),
                                 bf2(v01.x, v01.y), bf2(v11.x, v11.y));
            Al4[fi] = make_uint4(
                bf2(lo_of(v00.x), lo_of(v00.y)), bf2(lo_of(v10.x), lo_of(v10.y)),
                bf2(lo_of(v01.x), lo_of(v01.y)), bf2(lo_of(v11.x), lo_of(v11.y)));
        }
        __syncthreads();

        // ---- fused 3-pass MMA loop -----------------------------------------
        float4 acc[2][4];
#pragma unroll
        for (int mi = 0; mi < 2; mi++)
#pragma unroll
            for (int ni = 0; ni < 4; ni++)
                acc[mi][ni] = make_float4(0.f, 0.f, 0.f, 0.f);

        for (int kt = 0; kt < 16; kt++) {
            uint4 ah[2], al[2], bh[2], bl[2];
#pragma unroll
            for (int mi = 0; mi < 2; mi++) {
                ah[mi] = Ah4[(kt * 4 + mtg * 2 + mi) * 32 + lane];
                al[mi] = Al4[(kt * 4 + mtg * 2 + mi) * 32 + lane];
            }
#pragma unroll
            for (int p = 0; p < 2; p++) {
                bh[p] = Bh4[(kt * 8 + ntg * 2 + p) * 32 + lane];
                bl[p] = Bl4[(kt * 8 + ntg * 2 + p) * 32 + lane];
            }
#pragma unroll
            for (int mi = 0; mi < 2; mi++)
#pragma unroll
                for (int ni = 0; ni < 4; ni++) {
                    uint4 v = bh[ni >> 1];
                    mma16816(acc[mi][ni], ah[mi], (ni & 1) ? v.z : v.x,
                                                  (ni & 1) ? v.w : v.y);
                }
#pragma unroll
            for (int mi = 0; mi < 2; mi++)
#pragma unroll
                for (int ni = 0; ni < 4; ni++) {
                    uint4 v = bl[ni >> 1];
                    mma16816(acc[mi][ni], ah[mi], (ni & 1) ? v.z : v.x,
                                                  (ni & 1) ? v.w : v.y);
                }
#pragma unroll
            for (int mi = 0; mi < 2; mi++)
#pragma unroll
                for (int ni = 0; ni < 4; ni++) {
                    uint4 v = bh[ni >> 1];
                    mma16816(acc[mi][ni], al[mi], (ni & 1) ? v.z : v.x,
                                                  (ni & 1) ? v.w : v.y);
                }
        }

        // ---- epilogue -------------------------------------------------------
#pragma unroll
        for (int mi = 0; mi < 2; mi++) {
            int er0 = tb + (mtg * 2 + mi) * 16 + g;
            int er1 = er0 + 8;
            if (!POOL) {
#pragma unroll
                for (int ni = 0; ni < 4; ni++) {
                    int ch = ((ntg * 4 + ni) * 8 + tig * 2) >> 1;  // float2 col
                    float e00 = fmaxf(acc[mi][ni].x + bs[ni][0], 0.f);
                    float e01 = fmaxf(acc[mi][ni].y + bs[ni][1], 0.f);
                    float e10 = fmaxf(acc[mi][ni].z + bs[ni][0], 0.f);
                    float e11 = fmaxf(acc[mi][ni].w + bs[ni][1], 0.f);
                    if (er0 < kN) h1f2[er0 * 64 + ch] = make_float2(e00, e01);
                    if (er1 < kN) h1f2[er1 * 64 + ch] = make_float2(e10, e11);
                }
            } else {
                float s0 = 0.f, s1 = 0.f;
#pragma unroll
                for (int ni = 0; ni < 4; ni++) {
                    s0 += fmaxf(acc[mi][ni].x + bs[ni][0], 0.f) * wf[ni][0]
                        + fmaxf(acc[mi][ni].y + bs[ni][1], 0.f) * wf[ni][1];
                    s1 += fmaxf(acc[mi][ni].z + bs[ni][0], 0.f) * wf[ni][0]
                        + fmaxf(acc[mi][ni].w + bs[ni][1], 0.f) * wf[ni][1];
                }
                s0 += __shfl_xor_sync(~0u, s0, 1);
                s0 += __shfl_xor_sync(~0u, s0, 2);
                s1 += __shfl_xor_sync(~0u, s1, 1);
                s1 += __shfl_xor_sync(~0u, s1, 2);
                if (tig == 0) {
                    if (er0 < kN) atomicAdd(&g_gacc[batch[er0]], s0);
                    if (er1 < kN) atomicAdd(&g_gacc[batch[er1]], s1);
                }
            }
        }
    }
}

// ---- final readout + restore zero-invariant ---------------------------------
__global__ void k_final(const float* __restrict__ bfc, float* __restrict__ out) {
    int t = blockIdx.x * blockDim.x + threadIdx.x;
    if (blockIdx.x == 0 && threadIdx.x < kG) {
        int g = threadIdx.x;
        out[g] = g_gacc[g] / (float)max(g_gcnt[g], 1) + bfc[0];
        g_gacc[g] = 0.f;
        g_gcnt[g] = 0;
    }
    for (int i = t; i < kN; i += gridDim.x * blockDim.x) g_deg[i] = 0;
}

// ---- entry ------------------------------------------------------------------
extern "C" void kernel_launch(void* const* d_in, const int* in_sizes, int n_in,
                              void* d_out, int out_size) {
    const float4* x     = (const float4*)d_in[0];
    const int*    ei    = (const int*)d_in[1];    // int32 (JAX x64 disabled)
    const int*    batch = (const int*)d_in[2];
    const float*  W1l   = (const float*)d_in[3];
    const float*  b1    = (const float*)d_in[4];
    const float*  W1r   = (const float*)d_in[5];
    const float*  W2l   = (const float*)d_in[6];
    const float*  b2    = (const float*)d_in[7];
    const float*  W2r   = (const float*)d_in[8];
    const float*  Wfc   = (const float*)d_in[9];
    const float*  bfc   = (const float*)d_in[10];
    float*        out   = (float*)d_out;

    static int attr_done = 0;
    if (!attr_done) {
        cudaFuncSetAttribute(k_mma_layer<false>,
                             cudaFuncAttributeMaxDynamicSharedMemorySize, SMEMSZ);
        cudaFuncSetAttribute(k_mma_layer<true>,
                             cudaFuncAttributeMaxDynamicSharedMemorySize, SMEMSZ);
        attr_done = 1;
    }

    // CSR build (parallel 3-phase scan)
    k_count<<<512, 256>>>(ei, batch);
    k_scanA<<<SCANB, 1024>>>();
    k_scanB<<<1, 128>>>();
    k_scanC<<<SCANB, 1024>>>();
    k_fill<<<512, 256>>>(ei);

    // Layer 1
    k_gather<<<1024, 256>>>(x, 0);
    k_mma_layer<false><<<148, 256, SMEMSZ>>>(x, 0, W1l, b1, W1r, batch, Wfc);

    // Layer 2 (+ fused pooled readout)
    k_gather<<<1024, 256>>>(x, 1);
    k_mma_layer<true><<<148, 256, SMEMSZ>>>(x, 1, W2l, b2, W2r, batch, Wfc);

    k_final<<<512, 256>>>(bfc, out);
}

// round 17
// speedup vs baseline: 1.9134x; 1.1196x over previous
#include <cuda_runtime.h>
#include <cuda_bf16.h>

#define kN 100000
#define kE 1600000
#define kG 256
#define kT64 1563           // ceil(kN/64)
#define SCANB 98            // ceil(kN/1024)

// ---- scratch (static; no cudaMalloc). g_deg/g_gcnt/g_gacc zero at entry. ----
__device__ float4 g_agg[kN * 32];
__device__ float4 g_h1 [kN * 32];
__device__ int    g_deg[kN];
__device__ int    g_rowptr[kN + 1];
__device__ int    g_cursor[kN];
__device__ int    g_csr[kE];
__device__ int    g_bsum[SCANB];
__device__ int    g_gcnt[kG];
__device__ float  g_gacc[kG];
__device__ uint4  g_Bh[2][4096];    // pre-packed B fragments (hi), per layer
__device__ uint4  g_Bl[2][4096];    // pre-packed B fragments (lo), per layer

// ---- helpers ----------------------------------------------------------------
__device__ __forceinline__ unsigned bf2(float a, float b) {
    __nv_bfloat162 t = __floats2bfloat162_rn(a, b);
    return *(unsigned*)&t;
}
__device__ __forceinline__ float lo_of(float v) {
    return v - __bfloat162float(__float2bfloat16_rn(v));
}
// m16n8k16 row.col bf16 MMA, fp32 accum. float4& keeps accumulators in regs.
__device__ __forceinline__ void mma16816(float4& d, const uint4& a,
                                         unsigned b0, unsigned b1) {
    asm volatile(
        "mma.sync.aligned.m16n8k16.row.col.f32.bf16.bf16.f32 "
        "{%0,%1,%2,%3}, {%4,%5,%6,%7}, {%8,%9}, {%0,%1,%2,%3};"
        : "+f"(d.x), "+f"(d.y), "+f"(d.z), "+f"(d.w)
        : "r"(a.x), "r"(a.y), "r"(a.z), "r"(a.w), "r"(b0), "r"(b1));
}

// ---- CSR build --------------------------------------------------------------
__global__ void k_count(const int* __restrict__ ei, const int* __restrict__ batch) {
    int t = blockIdx.x * blockDim.x + threadIdx.x, st = gridDim.x * blockDim.x;
    const int* dstp = ei + kE;
    for (int e = t; e < kE; e += st) atomicAdd(&g_deg[dstp[e]], 1);
    for (int i = t; i < kN; i += st) atomicAdd(&g_gcnt[batch[i]], 1);
}
__global__ void k_scanA() {
    __shared__ int wsums[32];
    int tid = threadIdx.x, lane = tid & 31, w = tid >> 5;
    int i = blockIdx.x * 1024 + tid;
    int v = (i < kN) ? g_deg[i] : 0;
    int x = v;
#pragma unroll
    for (int off = 1; off < 32; off <<= 1) {
        int y = __shfl_up_sync(0xffffffffu, x, off);
        if (lane >= off) x += y;
    }
    if (lane == 31) wsums[w] = x;
    __syncthreads();
    if (w == 0) {
        int s = wsums[lane];
#pragma unroll
        for (int off = 1; off < 32; off <<= 1) {
            int y = __shfl_up_sync(0xffffffffu, s, off);
            if (lane >= off) s += y;
        }
        wsums[lane] = s;
    }
    __syncthreads();
    int incl = ((w > 0) ? wsums[w - 1] : 0) + x;
    if (i < kN) { g_rowptr[i + 1] = incl; g_cursor[i] = incl - v; }
    if (tid == 1023) g_bsum[blockIdx.x] = incl;
}
__global__ void k_scanB() {
    __shared__ int s[128];
    int t = threadIdx.x;
    int v = (t < SCANB) ? g_bsum[t] : 0;
    s[t] = v;
    __syncthreads();
#pragma unroll
    for (int off = 1; off < 128; off <<= 1) {
        int y = (t >= off) ? s[t - off] : 0;
        __syncthreads();
        s[t] += y;
        __syncthreads();
    }
    if (t < SCANB) g_bsum[t] = s[t] - v;
}
__global__ void k_scanC() {
    int i = blockIdx.x * 1024 + threadIdx.x;
    if (i < kN) {
        int base = g_bsum[blockIdx.x];
        g_rowptr[i + 1] += base;
        g_cursor[i]     += base;
    }
    if (i == 0) g_rowptr[0] = 0;
}
__global__ void k_fill(const int* __restrict__ ei) {
    int t = blockIdx.x * blockDim.x + threadIdx.x, st = gridDim.x * blockDim.x;
    for (int e = t; e < kE; e += st) {
        int pos = atomicAdd(&g_cursor[ei[kE + e]], 1);
        g_csr[pos] = ei[e];
    }
}

// ---- pre-pack B fragments for both layers (hi & lo splits) -------------------
__global__ void k_packB(const float* __restrict__ W1l, const float* __restrict__ W1r,
                        const float* __restrict__ W2l, const float* __restrict__ W2r) {
    int idx = blockIdx.x * blockDim.x + threadIdx.x;   // 0..8191
    if (idx >= 8192) return;
    int L = idx >> 12, i = idx & 4095;
    const float* Wl = L ? W2l : W1l;
    const float* Wr = L ? W2r : W1r;
    int l = i & 31, ntp = (i >> 5) & 7, kt = i >> 8;
    int k0 = kt * 16 + (l & 3) * 2;
    uint4 hv, lv;
#pragma unroll
    for (int p = 0; p < 2; p++) {
        int n = (ntp * 2 + p) * 8 + (l >> 2);
        const float* w0 = (k0 < 128) ? (Wl + k0 * 128 + n) : (Wr + (k0 - 128) * 128 + n);
        float a = w0[0], b = w0[128], c = w0[8 * 128], d = w0[9 * 128];
        unsigned h0 = bf2(a, b), h1 = bf2(c, d);
        unsigned l0 = bf2(lo_of(a), lo_of(b)), l1 = bf2(lo_of(c), lo_of(d));
        if (p == 0) { hv.x = h0; hv.y = h1; lv.x = l0; lv.y = l1; }
        else        { hv.z = h0; hv.w = h1; lv.z = l0; lv.w = l1; }
    }
    g_Bh[L][i] = hv;
    g_Bl[L][i] = lv;
}

// ---- gather (MLP4) ----------------------------------------------------------
__global__ void k_gather(const float4* __restrict__ feat_ext, int use_h1) {
    const float4* feat = use_h1 ? (const float4*)g_h1 : feat_ext;
    int gw = (blockIdx.x * blockDim.x + threadIdx.x) >> 5;
    int lane = threadIdx.x & 31;
    int nw = (gridDim.x * blockDim.x) >> 5;
    for (int node = gw; node < kN; node += nw) {
        int beg = g_rowptr[node], end = g_rowptr[node + 1];
        float4 a0 = make_float4(0.f, 0.f, 0.f, 0.f), a1 = a0;
        for (int b = beg; b < end; b += 32) {
            int e = b + lane;
            int idx = (e < end) ? g_csr[e] : 0;
            int cnt = min(32, end - b), i = 0;
            for (; i + 4 <= cnt; i += 4) {
                int s0 = __shfl_sync(~0u, idx, i),     s1 = __shfl_sync(~0u, idx, i + 1);
                int s2 = __shfl_sync(~0u, idx, i + 2), s3 = __shfl_sync(~0u, idx, i + 3);
                float4 v0 = __ldg(&feat[s0 * 32 + lane]), v1 = __ldg(&feat[s1 * 32 + lane]);
                float4 v2 = __ldg(&feat[s2 * 32 + lane]), v3 = __ldg(&feat[s3 * 32 + lane]);
                a0.x += v0.x; a0.y += v0.y; a0.z += v0.z; a0.w += v0.w;
                a1.x += v1.x; a1.y += v1.y; a1.z += v1.z; a1.w += v1.w;
                a0.x += v2.x; a0.y += v2.y; a0.z += v2.z; a0.w += v2.w;
                a1.x += v3.x; a1.y += v3.y; a1.z += v3.z; a1.w += v3.w;
            }
            for (; i < cnt; i++) {
                int s0 = __shfl_sync(~0u, idx, i);
                float4 v0 = __ldg(&feat[s0 * 32 + lane]);
                a0.x += v0.x; a0.y += v0.y; a0.z += v0.z; a0.w += v0.w;
            }
        }
        float di = 1.0f / (float)max(end - beg, 1);
        a0.x = (a0.x + a1.x) * di; a0.y = (a0.y + a1.y) * di;
        a0.z = (a0.z + a1.z) * di; a0.w = (a0.w + a1.w) * di;
        g_agg[node * 32 + lane] = a0;
    }
}

// ---- HMMA SAGE layer (M=64 tiles, B frags from L2, occupancy 2) -------------
// Per 64-row tile: D = Ah@Bh + Ah@Bl + Al@Bh fused in ONE kt loop (24 MMA/kt).
// B fragments live in GLOBAL memory (pre-packed, L2-resident, same for every
// tile) -> smem holds only Ah+Al (64 KB) -> 2 CTAs/SM: one CTA's pack phase
// overlaps the other's MMA phase. Fragment layouts unchanged (verified).
#define OFF_AH 0
#define OFF_AL 32768
#define SMEMSZ 65536
template <bool POOL>
__global__ void __launch_bounds__(256, 2)
k_mma_layer(const float4* __restrict__ xin_ext, int use_h1, int layer,
            const float* __restrict__ bias, const int* __restrict__ batch,
            const float* __restrict__ Wfc) {
    extern __shared__ unsigned char smem[];
    int tid = threadIdx.x, wid = tid >> 5, lane = tid & 31;
    int g = lane >> 2, tig = lane & 3;
    int mtg = wid >> 2, ntg = wid & 3;      // MMA: 2 mtg x 4 ntg
    const float2* agg2 = (const float2*)g_agg;
    const float2* xin2 = use_h1 ? (const float2*)g_h1 : (const float2*)xin_ext;
    float2* h1f2 = (float2*)g_h1;
    const uint4* Bh = g_Bh[layer];
    const uint4* Bl = g_Bl[layer];

    // per-lane column constants (cols c(ni) = (ntg*4+ni)*8 + tig*2, +1)
    float bs[4][2], wf[4][2];
#pragma unroll
    for (int ni = 0; ni < 4; ni++) {
        int c = (ntg * 4 + ni) * 8 + tig * 2;
        bs[ni][0] = bias[c]; bs[ni][1] = bias[c + 1];
        wf[ni][0] = POOL ? Wfc[c] : 0.f;
        wf[ni][1] = POOL ? Wfc[c + 1] : 0.f;
    }

    uint4* Ah4 = (uint4*)(smem + OFF_AH);
    uint4* Al4 = (uint4*)(smem + OFF_AL);
    int pmt = wid & 3, pkh = wid >> 2;      // pack: warp -> m-tile pmt, kt-half pkh

    for (int tile = blockIdx.x; tile < kT64; tile += gridDim.x) {
        int tb = tile << 6;
        int r0 = tb + pmt * 16 + g, r1 = r0 + 8;
        bool ok0 = r0 < kN, ok1 = r1 < kN;
        const float2* pa0 = agg2 + (size_t)r0 * 64;
        const float2* pa1 = agg2 + (size_t)r1 * 64;
        const float2* px0 = xin2 + (size_t)r0 * 64;
        const float2* px1 = xin2 + (size_t)r1 * 64;
        const float2 z2 = make_float2(0.f, 0.f);

        __syncthreads();                    // protect A buffers from prev tile
        // ---- single pack phase: hi AND lo from one read ---------------------
#pragma unroll
        for (int ki = 0; ki < 8; ki++) {
            int kt = pkh * 8 + ki;
            const float2* s0 = (kt < 8) ? pa0 : px0;
            const float2* s1 = (kt < 8) ? pa1 : px1;
            int t0 = (kt & 7) * 8 + tig;
            float2 v00 = ok0 ? __ldg(&s0[t0])     : z2;
            float2 v01 = ok0 ? __ldg(&s0[t0 + 4]) : z2;
            float2 v10 = ok1 ? __ldg(&s1[t0])     : z2;
            float2 v11 = ok1 ? __ldg(&s1[t0 + 4]) : z2;
            int fi = (kt * 4 + pmt) * 32 + lane;
            Ah4[fi] = make_uint4(bf2(v00.x, v00.y), bf2(v10.x, v10.y),
                                 bf2(v01.x, v01.y), bf2(v11.x, v11.y));
            Al4[fi] = make_uint4(
                bf2(lo_of(v00.x), lo_of(v00.y)), bf2(lo_of(v10.x), lo_of(v10.y)),
                bf2(lo_of(v01.x), lo_of(v01.y)), bf2(lo_of(v11.x), lo_of(v11.y)));
        }
        __syncthreads();

        // ---- fused 3-pass MMA loop (B frags via L2) -------------------------
        float4 acc[2][4];
#pragma unroll
        for (int mi = 0; mi < 2; mi++)
#pragma unroll
            for (int ni = 0; ni < 4; ni++)
                acc[mi][ni] = make_float4(0.f, 0.f, 0.f, 0.f);

        for (int kt = 0; kt < 16; kt++) {
            uint4 ah[2], al[2], bh[2], bl[2];
#pragma unroll
            for (int p = 0; p < 2; p++) {
                bh[p] = __ldg(&Bh[(kt * 8 + ntg * 2 + p) * 32 + lane]);
                bl[p] = __ldg(&Bl[(kt * 8 + ntg * 2 + p) * 32 + lane]);
            }
#pragma unroll
            for (int mi = 0; mi < 2; mi++) {
                ah[mi] = Ah4[(kt * 4 + mtg * 2 + mi) * 32 + lane];
                al[mi] = Al4[(kt * 4 + mtg * 2 + mi) * 32 + lane];
            }
#pragma unroll
            for (int mi = 0; mi < 2; mi++)
#pragma unroll
                for (int ni = 0; ni < 4; ni++) {
                    uint4 v = bh[ni >> 1];
                    mma16816(acc[mi][ni], ah[mi], (ni & 1) ? v.z : v.x,
                                                  (ni & 1) ? v.w : v.y);
                }
#pragma unroll
            for (int mi = 0; mi < 2; mi++)
#pragma unroll
                for (int ni = 0; ni < 4; ni++) {
                    uint4 v = bl[ni >> 1];
                    mma16816(acc[mi][ni], ah[mi], (ni & 1) ? v.z : v.x,
                                                  (ni & 1) ? v.w : v.y);
                }
#pragma unroll
            for (int mi = 0; mi < 2; mi++)
#pragma unroll
                for (int ni = 0; ni < 4; ni++) {
                    uint4 v = bh[ni >> 1];
                    mma16816(acc[mi][ni], al[mi], (ni & 1) ? v.z : v.x,
                                                  (ni & 1) ? v.w : v.y);
                }
        }

        // ---- epilogue -------------------------------------------------------
#pragma unroll
        for (int mi = 0; mi < 2; mi++) {
            int er0 = tb + (mtg * 2 + mi) * 16 + g;
            int er1 = er0 + 8;
            if (!POOL) {
#pragma unroll
                for (int ni = 0; ni < 4; ni++) {
                    int ch = ((ntg * 4 + ni) * 8 + tig * 2) >> 1;  // float2 col
                    float e00 = fmaxf(acc[mi][ni].x + bs[ni][0], 0.f);
                    float e01 = fmaxf(acc[mi][ni].y + bs[ni][1], 0.f);
                    float e10 = fmaxf(acc[mi][ni].z + bs[ni][0], 0.f);
                    float e11 = fmaxf(acc[mi][ni].w + bs[ni][1], 0.f);
                    if (er0 < kN) h1f2[er0 * 64 + ch] = make_float2(e00, e01);
                    if (er1 < kN) h1f2[er1 * 64 + ch] = make_float2(e10, e11);
                }
            } else {
                float s0 = 0.f, s1 = 0.f;
#pragma unroll
                for (int ni = 0; ni < 4; ni++) {
                    s0 += fmaxf(acc[mi][ni].x + bs[ni][0], 0.f) * wf[ni][0]
                        + fmaxf(acc[mi][ni].y + bs[ni][1], 0.f) * wf[ni][1];
                    s1 += fmaxf(acc[mi][ni].z + bs[ni][0], 0.f) * wf[ni][0]
                        + fmaxf(acc[mi][ni].w + bs[ni][1], 0.f) * wf[ni][1];
                }
                s0 += __shfl_xor_sync(~0u, s0, 1);
                s0 += __shfl_xor_sync(~0u, s0, 2);
                s1 += __shfl_xor_sync(~0u, s1, 1);
                s1 += __shfl_xor_sync(~0u, s1, 2);
                if (tig == 0) {
                    if (er0 < kN) atomicAdd(&g_gacc[batch[er0]], s0);
                    if (er1 < kN) atomicAdd(&g_gacc[batch[er1]], s1);
                }
            }
        }
    }
}

// ---- final readout + restore zero-invariant ---------------------------------
__global__ void k_final(const float* __restrict__ bfc, float* __restrict__ out) {
    int t = blockIdx.x * blockDim.x + threadIdx.x;
    if (blockIdx.x == 0 && threadIdx.x < kG) {
        int g = threadIdx.x;
        out[g] = g_gacc[g] / (float)max(g_gcnt[g], 1) + bfc[0];
        g_gacc[g] = 0.f;
        g_gcnt[g] = 0;
    }
    for (int i = t; i < kN; i += gridDim.x * blockDim.x) g_deg[i] = 0;
}

// ---- entry ------------------------------------------------------------------
extern "C" void kernel_launch(void* const* d_in, const int* in_sizes, int n_in,
                              void* d_out, int out_size) {
    const float4* x     = (const float4*)d_in[0];
    const int*    ei    = (const int*)d_in[1];    // int32 (JAX x64 disabled)
    const int*    batch = (const int*)d_in[2];
    const float*  W1l   = (const float*)d_in[3];
    const float*  b1    = (const float*)d_in[4];
    const float*  W1r   = (const float*)d_in[5];
    const float*  W2l   = (const float*)d_in[6];
    const float*  b2    = (const float*)d_in[7];
    const float*  W2r   = (const float*)d_in[8];
    const float*  Wfc   = (const float*)d_in[9];
    const float*  bfc   = (const float*)d_in[10];
    float*        out   = (float*)d_out;

    static int attr_done = 0;
    if (!attr_done) {
        cudaFuncSetAttribute(k_mma_layer<false>,
                             cudaFuncAttributeMaxDynamicSharedMemorySize, SMEMSZ);
        cudaFuncSetAttribute(k_mma_layer<true>,
                             cudaFuncAttributeMaxDynamicSharedMemorySize, SMEMSZ);
        attr_done = 1;
    }

    // CSR build + weight fragment pre-pack
    k_count<<<512, 256>>>(ei, batch);
    k_scanA<<<SCANB, 1024>>>();
    k_scanB<<<1, 128>>>();
    k_scanC<<<SCANB, 1024>>>();
    k_fill<<<512, 256>>>(ei);
    k_packB<<<32, 256>>>(W1l, W1r, W2l, W2r);

    // Layer 1
    k_gather<<<1024, 256>>>(x, 0);
    k_mma_layer<false><<<296, 256, SMEMSZ>>>(x, 0, 0, b1, batch, Wfc);

    // Layer 2 (+ fused pooled readout)
    k_gather<<<1024, 256>>>(x, 1);
    k_mma_layer<true><<<296, 256, SMEMSZ>>>(x, 1, 1, b2, batch, Wfc);

    k_final<<<512, 256>>>(bfc, out);
}